// round 1
// baseline (speedup 1.0000x reference)
#include <cuda_runtime.h>

#define Bx 8
#define Nn 1024
#define Fdim 256
#define OUTd 256
#define RELd 16
#define Rr 7

// Scratch: HW[r][b][n][o], 7*8*1024*256 floats = 56 MB
__device__ float g_HW[Rr * Bx * Nn * OUTd];
__device__ float g_c[Rr * OUTd];

// ---------------------------------------------------------------------------
// c[r][o] = sum_d W_edges[r,d] * W[r, F+d, o]
__global__ void c_kernel(const float* __restrict__ W, const float* __restrict__ We) {
    int r = blockIdx.x;
    int o = threadIdx.x;
    float s = 0.f;
#pragma unroll
    for (int d = 0; d < RELd; d++)
        s += We[r * RELd + d] * W[(r * (Fdim + RELd) + Fdim + d) * OUTd + o];
    g_c[r * OUTd + o] = s;
}

// ---------------------------------------------------------------------------
// HW[r][b][n][o] = X[b,n,:] @ W[r][:F, o] + c[r][o]
// GEMM: M=8192 rows (b,n), K=256, cols laid out as j = r*256 + o (1792 cols).
// 64x64 tile per block, 256 threads, 4x4 micro-tile, TK=16.
__global__ void hw_kernel(const float* __restrict__ X, const float* __restrict__ W) {
    const int col0 = blockIdx.x * 64;       // within [0,1792)
    const int row0 = blockIdx.y * 64;       // within [0,8192)
    const int r  = col0 / OUTd;             // 64-col tile never crosses r (256%64==0)
    const int o0 = col0 % OUTd;
    const float* Wr = W + r * (Fdim + RELd) * OUTd;

    __shared__ float sX[16][64];            // [k][m]
    __shared__ float sW[16][64];            // [k][o]

    const int tid = threadIdx.x;
    const int tx = tid & 15;                // micro-tile col group
    const int ty = tid >> 4;                // micro-tile row group

    float acc[4][4];
#pragma unroll
    for (int i = 0; i < 4; i++)
#pragma unroll
        for (int j = 0; j < 4; j++) acc[i][j] = 0.f;

    for (int k0 = 0; k0 < Fdim; k0 += 16) {
        {   // load X tile (transpose store)
            int m = tid >> 2, kg = (tid & 3) * 4;
            float4 v = *(const float4*)&X[(size_t)(row0 + m) * Fdim + k0 + kg];
            sX[kg + 0][m] = v.x; sX[kg + 1][m] = v.y;
            sX[kg + 2][m] = v.z; sX[kg + 3][m] = v.w;
        }
        {   // load W tile
            int k = tid >> 4, og = (tid & 15) * 4;
            *(float4*)&sW[k][og] = *(const float4*)&Wr[(size_t)(k0 + k) * OUTd + o0 + og];
        }
        __syncthreads();
#pragma unroll
        for (int k = 0; k < 16; k++) {
            float4 a = *(const float4*)&sX[k][ty * 4];
            float4 h = *(const float4*)&sW[k][tx * 4];
            acc[0][0] += a.x * h.x; acc[0][1] += a.x * h.y; acc[0][2] += a.x * h.z; acc[0][3] += a.x * h.w;
            acc[1][0] += a.y * h.x; acc[1][1] += a.y * h.y; acc[1][2] += a.y * h.z; acc[1][3] += a.y * h.w;
            acc[2][0] += a.z * h.x; acc[2][1] += a.z * h.y; acc[2][2] += a.z * h.z; acc[2][3] += a.z * h.w;
            acc[3][0] += a.w * h.x; acc[3][1] += a.w * h.y; acc[3][2] += a.w * h.z; acc[3][3] += a.w * h.w;
        }
        __syncthreads();
    }

    float4 cv = *(const float4*)&g_c[r * OUTd + o0 + tx * 4];
#pragma unroll
    for (int i = 0; i < 4; i++) {
        int row = row0 + ty * 4 + i;
        int b = row >> 10, n = row & 1023;
        float4 v;
        v.x = acc[i][0] + cv.x; v.y = acc[i][1] + cv.y;
        v.z = acc[i][2] + cv.z; v.w = acc[i][3] + cv.w;
        *(float4*)&g_HW[(((size_t)(r * Bx + b) * Nn + n) * OUTd) + o0 + tx * 4] = v;
    }
}

// ---------------------------------------------------------------------------
// out[b,n,o] = max( A1@HW0, A2@HW1, A1t@HW3, A2t@HW4, HW2, HW5, HW6 )[b,n,o] + bias[n,o]
// Per block: one b, 64x64 (n,o) tile. 4 sequential matmul passes with running max.
__global__ void agg_kernel(const float* __restrict__ A1, const float* __restrict__ A2,
                           const float* __restrict__ bias, float* __restrict__ out) {
    const int b  = blockIdx.z;
    const int n0 = blockIdx.y * 64;
    const int o0 = blockIdx.x * 64;
    const int tid = threadIdx.x;
    const int tx = tid & 15;
    const int ty = tid >> 4;

    __shared__ float sA[16][64];            // [k][n]
    __shared__ float sH[16][64];            // [k][o]

    float mx[4][4];

#pragma unroll
    for (int p = 0; p < 4; p++) {
        const float* A = ((p == 0 || p == 2) ? A1 : A2) + (size_t)b * Nn * Nn;
        const int hwr  = (p == 0) ? 0 : (p == 1) ? 1 : (p == 2) ? 3 : 4;
        const bool trans = (p >= 2);
        const float* H = g_HW + ((size_t)(hwr * Bx + b) * Nn) * OUTd;

        float acc[4][4];
#pragma unroll
        for (int i = 0; i < 4; i++)
#pragma unroll
            for (int j = 0; j < 4; j++) acc[i][j] = 0.f;

        for (int m0 = 0; m0 < Nn; m0 += 16) {
            if (!trans) {
                // sA[k][n] = A[b, n0+n, m0+k] : load along m (coalesced), scatter
                int n = tid >> 2, kg = (tid & 3) * 4;
                float4 v = *(const float4*)&A[(size_t)(n0 + n) * Nn + m0 + kg];
                sA[kg + 0][n] = v.x; sA[kg + 1][n] = v.y;
                sA[kg + 2][n] = v.z; sA[kg + 3][n] = v.w;
            } else {
                // sA[k][n] = A[b, m0+k, n0+n] : coalesced along n
                int k = tid >> 4, ng = (tid & 15) * 4;
                *(float4*)&sA[k][ng] = *(const float4*)&A[(size_t)(m0 + k) * Nn + n0 + ng];
            }
            {
                int k = tid >> 4, og = (tid & 15) * 4;
                *(float4*)&sH[k][og] = *(const float4*)&H[(size_t)(m0 + k) * OUTd + o0 + og];
            }
            __syncthreads();
#pragma unroll
            for (int k = 0; k < 16; k++) {
                float4 a = *(const float4*)&sA[k][ty * 4];
                float4 h = *(const float4*)&sH[k][tx * 4];
                acc[0][0] += a.x * h.x; acc[0][1] += a.x * h.y; acc[0][2] += a.x * h.z; acc[0][3] += a.x * h.w;
                acc[1][0] += a.y * h.x; acc[1][1] += a.y * h.y; acc[1][2] += a.y * h.z; acc[1][3] += a.y * h.w;
                acc[2][0] += a.z * h.x; acc[2][1] += a.z * h.y; acc[2][2] += a.z * h.z; acc[2][3] += a.z * h.w;
                acc[3][0] += a.w * h.x; acc[3][1] += a.w * h.y; acc[3][2] += a.w * h.z; acc[3][3] += a.w * h.w;
            }
            __syncthreads();
        }

        if (p == 0) {
#pragma unroll
            for (int i = 0; i < 4; i++)
#pragma unroll
                for (int j = 0; j < 4; j++) mx[i][j] = acc[i][j];
        } else {
#pragma unroll
            for (int i = 0; i < 4; i++)
#pragma unroll
                for (int j = 0; j < 4; j++) mx[i][j] = fmaxf(mx[i][j], acc[i][j]);
        }
    }

    // identity relations (2,5,6) + bias + writeback
    const size_t base2 = ((size_t)(2 * Bx + b) * Nn) * OUTd;
    const size_t base5 = ((size_t)(5 * Bx + b) * Nn) * OUTd;
    const size_t base6 = ((size_t)(6 * Bx + b) * Nn) * OUTd;
#pragma unroll
    for (int i = 0; i < 4; i++) {
        int n = n0 + ty * 4 + i;
        size_t off = (size_t)n * OUTd + o0 + tx * 4;
        float4 h2 = *(const float4*)&g_HW[base2 + off];
        float4 h5 = *(const float4*)&g_HW[base5 + off];
        float4 h6 = *(const float4*)&g_HW[base6 + off];
        float4 bb = *(const float4*)&bias[off];
        float4 v;
        v.x = fmaxf(fmaxf(mx[i][0], h2.x), fmaxf(h5.x, h6.x)) + bb.x;
        v.y = fmaxf(fmaxf(mx[i][1], h2.y), fmaxf(h5.y, h6.y)) + bb.y;
        v.z = fmaxf(fmaxf(mx[i][2], h2.z), fmaxf(h5.z, h6.z)) + bb.z;
        v.w = fmaxf(fmaxf(mx[i][3], h2.w), fmaxf(h5.w, h6.w)) + bb.w;
        *(float4*)&out[(size_t)b * Nn * OUTd + off] = v;
    }
}

// ---------------------------------------------------------------------------
extern "C" void kernel_launch(void* const* d_in, const int* in_sizes, int n_in,
                              void* d_out, int out_size) {
    const float* X    = (const float*)d_in[0];   // [8,1024,256]
    const float* A1   = (const float*)d_in[1];   // [8,1024,1024]
    const float* A2   = (const float*)d_in[2];   // [8,1024,1024]
    const float* W    = (const float*)d_in[3];   // [7,272,256]
    const float* We   = (const float*)d_in[4];   // [7,16]
    const float* bias = (const float*)d_in[5];   // [1024,256]
    float* out = (float*)d_out;                  // [8,1024,256]

    c_kernel<<<Rr, OUTd>>>(W, We);

    dim3 gHW(28, 128);                           // 1792/64 cols, 8192/64 rows
    hw_kernel<<<gHW, 256>>>(X, W);

    dim3 gAgg(4, 16, 8);                         // 256/64 o-tiles, 1024/64 n-tiles, 8 b
    agg_kernel<<<gAgg, 256>>>(A1, A2, bias, out);
}

// round 3
// speedup vs baseline: 2.5582x; 2.5582x over previous
#include <cuda_runtime.h>
#include <cstdint>
#include <cfloat>

#define Bx 8
#define Nn 1024
#define Fdim 256
#define OUTd 256
#define RELd 16
#define Rr 7

#define KC 32
#define SA_STR 36     // sA[n][k]  (row-major A), pad 4
#define ST_STR 136    // sAT[k][n] (transposed A) and sB[k][o], pad 8

// A-buffer: max(128*36, 32*136) = 4608 floats; B-buffer: 32*136 = 4352 floats
#define ABUF 4608
#define BBUF 4352
#define SMEM_FLOATS (2 * ABUF + 2 * BBUF)   // 17920 floats = 71680 B

// H[r][b][n][o], o contiguous
__device__ float g_H[Rr * Bx * Nn * OUTd];  // 56 MB
__device__ float g_c[Rr * OUTd];

__device__ __forceinline__ float to_tf32(float x) {
    float y; asm("cvt.rna.tf32.f32 %0, %1;" : "=f"(y) : "f"(x)); return y;
}
__device__ __forceinline__ float4 round4(float4 v) {
    v.x = to_tf32(v.x); v.y = to_tf32(v.y); v.z = to_tf32(v.z); v.w = to_tf32(v.w);
    return v;
}
__device__ __forceinline__ void mma8(float* c, const uint32_t* a, uint32_t b0, uint32_t b1) {
    asm volatile(
        "mma.sync.aligned.m16n8k8.row.col.f32.tf32.tf32.f32 "
        "{%0,%1,%2,%3}, {%4,%5,%6,%7}, {%8,%9}, {%0,%1,%2,%3};"
        : "+f"(c[0]), "+f"(c[1]), "+f"(c[2]), "+f"(c[3])
        : "r"(a[0]), "r"(a[1]), "r"(a[2]), "r"(a[3]), "r"(b0), "r"(b1));
}
__device__ __forceinline__ uint32_t fbits(const float* p) { return *(const uint32_t*)p; }

// ---------------------------------------------------------------------------
__global__ void c_kernel(const float* __restrict__ W, const float* __restrict__ We) {
    int r = blockIdx.x, o = threadIdx.x;
    float s = 0.f;
#pragma unroll
    for (int d = 0; d < RELd; d++)
        s += We[r * RELd + d] * W[(r * (Fdim + RELd) + Fdim + d) * OUTd + o];
    g_c[r * OUTd + o] = s;
}

// ---------------------------------------------------------------------------
// HW GEMM: g_H[r][b][n][o] = X[b,n,:]@W[r][:F] + c[r].  CTA tile 128(m) x 128(o).
__global__ __launch_bounds__(256) void hw_mma(const float* __restrict__ X,
                                              const float* __restrict__ W) {
    extern __shared__ float sm[];
    float* sA[2] = { sm, sm + ABUF };
    float* sB[2] = { sm + 2 * ABUF, sm + 2 * ABUF + BBUF };

    const int tid = threadIdx.x, lane = tid & 31, wid = tid >> 5;
    const int warp_m = (wid & 3) * 32, warp_n = (wid >> 2) * 64;
    const int grp = lane >> 2, tg = lane & 3;

    const int col0 = blockIdx.x * 128;
    const int m0   = blockIdx.y * 128;
    const int r    = col0 >> 8;
    const int o0   = col0 & 255;
    const float* Wr = W + (size_t)r * (Fdim + RELd) * OUTd;

    float acc[2][8][4];
#pragma unroll
    for (int mt = 0; mt < 2; mt++)
#pragma unroll
        for (int nt = 0; nt < 8; nt++)
#pragma unroll
            for (int j = 0; j < 4; j++) acc[mt][nt][j] = 0.f;

    // prologue: chunk 0 -> buf 0
#pragma unroll
    for (int i = 0; i < 4; i++) {
        int f = tid + i * 256, m = f >> 3, k4 = (f & 7) << 2;
        float4 v = round4(*(const float4*)(X + (size_t)(m0 + m) * Fdim + k4));
        *(float4*)(sA[0] + m * SA_STR + k4) = v;
        int kb = f >> 5, ob4 = (f & 31) << 2;
        float4 w = round4(*(const float4*)(Wr + (size_t)kb * OUTd + o0 + ob4));
        *(float4*)(sB[0] + kb * ST_STR + ob4) = w;
    }
    __syncthreads();

    const int NC = Fdim / KC;  // 8
    for (int c = 0; c < NC; c++) {
        const int buf = c & 1;
        float4 ra[4], rb[4];
        const bool pre = (c + 1 < NC);
        if (pre) {
            const int k0 = (c + 1) * KC;
#pragma unroll
            for (int i = 0; i < 4; i++) {
                int f = tid + i * 256, m = f >> 3, k4 = (f & 7) << 2;
                ra[i] = *(const float4*)(X + (size_t)(m0 + m) * Fdim + k0 + k4);
                int kb = f >> 5, ob4 = (f & 31) << 2;
                rb[i] = *(const float4*)(Wr + (size_t)(k0 + kb) * OUTd + o0 + ob4);
            }
        }
        const float* cA = sA[buf];
        const float* cB = sB[buf];
#pragma unroll
        for (int ks = 0; ks < 4; ks++) {
            const int k = ks * 8;
            uint32_t afr[2][4];
#pragma unroll
            for (int mt = 0; mt < 2; mt++) {
                int rr = warp_m + mt * 16 + grp, cc = k + tg;
                afr[mt][0] = fbits(cA + rr * SA_STR + cc);
                afr[mt][1] = fbits(cA + (rr + 8) * SA_STR + cc);
                afr[mt][2] = fbits(cA + rr * SA_STR + cc + 4);
                afr[mt][3] = fbits(cA + (rr + 8) * SA_STR + cc + 4);
            }
#pragma unroll
            for (int nt = 0; nt < 8; nt++) {
                int o = warp_n + nt * 8 + grp;
                uint32_t b0 = fbits(cB + (k + tg) * ST_STR + o);
                uint32_t b1 = fbits(cB + (k + tg + 4) * ST_STR + o);
                mma8(acc[0][nt], afr[0], b0, b1);
                mma8(acc[1][nt], afr[1], b0, b1);
            }
        }
        if (pre) {
            float* nA = sA[buf ^ 1];
            float* nB = sB[buf ^ 1];
#pragma unroll
            for (int i = 0; i < 4; i++) {
                int f = tid + i * 256, m = f >> 3, k4 = (f & 7) << 2;
                *(float4*)(nA + m * SA_STR + k4) = round4(ra[i]);
                int kb = f >> 5, ob4 = (f & 31) << 2;
                *(float4*)(nB + kb * ST_STR + ob4) = round4(rb[i]);
            }
            __syncthreads();
        }
    }

    // epilogue: += c[r], store g_H  (float2 per row, 32B sectors)
#pragma unroll
    for (int mt = 0; mt < 2; mt++) {
#pragma unroll
        for (int nt = 0; nt < 8; nt++) {
            const int o = o0 + warp_n + nt * 8 + 2 * tg;
            const float2 cv = *(const float2*)(g_c + r * OUTd + o);
            int mg = m0 + warp_m + mt * 16 + grp;
            int b = mg >> 10, n = mg & 1023;
            float* dst = g_H + (((size_t)(r * Bx + b) * Nn + n) * OUTd) + o;
            *(float2*)dst = make_float2(acc[mt][nt][0] + cv.x, acc[mt][nt][1] + cv.y);
            mg += 8; b = mg >> 10; n = mg & 1023;
            dst = g_H + (((size_t)(r * Bx + b) * Nn + n) * OUTd) + o;
            *(float2*)dst = make_float2(acc[mt][nt][2] + cv.x, acc[mt][nt][3] + cv.y);
        }
    }
}

// ---------------------------------------------------------------------------
// Aggregation: out[b][n][o] = max over {A1@H0, A2@H1, A1t@H3, A2t@H4, H2,H5,H6} + bias
// CTA tile 128(n) x 128(o); 4 sequential passes w/ running max in regs.
__global__ __launch_bounds__(256) void agg_mma(const float* __restrict__ A1,
                                               const float* __restrict__ A2,
                                               const float* __restrict__ bias,
                                               float* __restrict__ out) {
    extern __shared__ float sm[];
    float* sA[2] = { sm, sm + ABUF };
    float* sB[2] = { sm + 2 * ABUF, sm + 2 * ABUF + BBUF };

    const int tid = threadIdx.x, lane = tid & 31, wid = tid >> 5;
    const int warp_m = (wid & 3) * 32, warp_n = (wid >> 2) * 64;
    const int grp = lane >> 2, tg = lane & 3;

    const int o0 = blockIdx.x * 128;
    const int n0 = blockIdx.y * 128;
    const int b  = blockIdx.z;
    const float* Amat[2] = { A1 + (size_t)b * Nn * Nn, A2 + (size_t)b * Nn * Nn };

    float mx[2][8][4];
#pragma unroll
    for (int mt = 0; mt < 2; mt++)
#pragma unroll
        for (int nt = 0; nt < 8; nt++)
#pragma unroll
            for (int j = 0; j < 4; j++) mx[mt][nt][j] = -FLT_MAX;

    const int NC = Nn / KC;  // 32

#pragma unroll
    for (int half = 0; half < 2; half++) {          // compile-time: 0 = A@H, 1 = A^T@H
        for (int q = 0; q < 2; q++) {               // runtime: A1 / A2
            const float* Ab = Amat[q];
            const float* Hb = g_H + ((size_t)((half * 3 + q) * Bx + b) * Nn) * OUTd;

            float acc[2][8][4];
#pragma unroll
            for (int mt = 0; mt < 2; mt++)
#pragma unroll
                for (int nt = 0; nt < 8; nt++)
#pragma unroll
                    for (int j = 0; j < 4; j++) acc[mt][nt][j] = 0.f;

            __syncthreads();                        // buffers free from previous pass
            // prologue: chunk 0 -> buf 0
#pragma unroll
            for (int i = 0; i < 4; i++) {
                int f = tid + i * 256;
                if (half == 0) {
                    int m = f >> 3, k4 = (f & 7) << 2;
                    float4 v = round4(*(const float4*)(Ab + (size_t)(n0 + m) * Nn + k4));
                    *(float4*)(sA[0] + m * SA_STR + k4) = v;
                } else {
                    int kk = f >> 5, n4 = (f & 31) << 2;
                    float4 v = round4(*(const float4*)(Ab + (size_t)kk * Nn + n0 + n4));
                    *(float4*)(sA[0] + kk * ST_STR + n4) = v;
                }
                int kb = f >> 5, ob4 = (f & 31) << 2;
                float4 h = round4(*(const float4*)(Hb + (size_t)kb * OUTd + o0 + ob4));
                *(float4*)(sB[0] + kb * ST_STR + ob4) = h;
            }
            __syncthreads();

            for (int c = 0; c < NC; c++) {
                const int buf = c & 1;
                float4 ra[4], rb[4];
                const bool pre = (c + 1 < NC);
                if (pre) {
                    const int k0 = (c + 1) * KC;
#pragma unroll
                    for (int i = 0; i < 4; i++) {
                        int f = tid + i * 256;
                        if (half == 0) {
                            int m = f >> 3, k4 = (f & 7) << 2;
                            ra[i] = *(const float4*)(Ab + (size_t)(n0 + m) * Nn + k0 + k4);
                        } else {
                            int kk = f >> 5, n4 = (f & 31) << 2;
                            ra[i] = *(const float4*)(Ab + (size_t)(k0 + kk) * Nn + n0 + n4);
                        }
                        int kb = f >> 5, ob4 = (f & 31) << 2;
                        rb[i] = *(const float4*)(Hb + (size_t)(k0 + kb) * OUTd + o0 + ob4);
                    }
                }
                const float* cA = sA[buf];
                const float* cB = sB[buf];
#pragma unroll
                for (int ks = 0; ks < 4; ks++) {
                    const int k = ks * 8;
                    uint32_t afr[2][4];
#pragma unroll
                    for (int mt = 0; mt < 2; mt++) {
                        int rr = warp_m + mt * 16 + grp, cc = k + tg;
                        if (half == 0) {
                            afr[mt][0] = fbits(cA + rr * SA_STR + cc);
                            afr[mt][1] = fbits(cA + (rr + 8) * SA_STR + cc);
                            afr[mt][2] = fbits(cA + rr * SA_STR + cc + 4);
                            afr[mt][3] = fbits(cA + (rr + 8) * SA_STR + cc + 4);
                        } else {
                            afr[mt][0] = fbits(cA + cc * ST_STR + rr);
                            afr[mt][1] = fbits(cA + cc * ST_STR + rr + 8);
                            afr[mt][2] = fbits(cA + (cc + 4) * ST_STR + rr);
                            afr[mt][3] = fbits(cA + (cc + 4) * ST_STR + rr + 8);
                        }
                    }
#pragma unroll
                    for (int nt = 0; nt < 8; nt++) {
                        int o = warp_n + nt * 8 + grp;
                        uint32_t b0 = fbits(cB + (k + tg) * ST_STR + o);
                        uint32_t b1 = fbits(cB + (k + tg + 4) * ST_STR + o);
                        mma8(acc[0][nt], afr[0], b0, b1);
                        mma8(acc[1][nt], afr[1], b0, b1);
                    }
                }
                if (pre) {
                    float* nA = sA[buf ^ 1];
                    float* nB = sB[buf ^ 1];
#pragma unroll
                    for (int i = 0; i < 4; i++) {
                        int f = tid + i * 256;
                        if (half == 0) {
                            int m = f >> 3, k4 = (f & 7) << 2;
                            *(float4*)(nA + m * SA_STR + k4) = round4(ra[i]);
                        } else {
                            int kk = f >> 5, n4 = (f & 31) << 2;
                            *(float4*)(nA + kk * ST_STR + n4) = round4(ra[i]);
                        }
                        int kb = f >> 5, ob4 = (f & 31) << 2;
                        *(float4*)(nB + kb * ST_STR + ob4) = round4(rb[i]);
                    }
                    __syncthreads();
                }
            }
            // fold into running max
#pragma unroll
            for (int mt = 0; mt < 2; mt++)
#pragma unroll
                for (int nt = 0; nt < 8; nt++)
#pragma unroll
                    for (int j = 0; j < 4; j++)
                        mx[mt][nt][j] = fmaxf(mx[mt][nt][j], acc[mt][nt][j]);
        }
    }

    // epilogue: identity relations (2,5,6) + bias, write out
    const float* I2 = g_H + ((size_t)(2 * Bx + b) * Nn) * OUTd;
    const float* I5 = g_H + ((size_t)(5 * Bx + b) * Nn) * OUTd;
    const float* I6 = g_H + ((size_t)(6 * Bx + b) * Nn) * OUTd;
#pragma unroll
    for (int mt = 0; mt < 2; mt++) {
#pragma unroll
        for (int nt = 0; nt < 8; nt++) {
            const int o = o0 + warp_n + nt * 8 + 2 * tg;
#pragma unroll
            for (int h = 0; h < 2; h++) {
                const int n = n0 + warp_m + mt * 16 + grp + h * 8;
                const size_t off = (size_t)n * OUTd + o;
                float2 v2 = *(const float2*)(I2 + off);
                float2 v5 = *(const float2*)(I5 + off);
                float2 v6 = *(const float2*)(I6 + off);
                float2 bb = *(const float2*)(bias + off);
                float x = fmaxf(fmaxf(mx[mt][nt][2 * h], v2.x), fmaxf(v5.x, v6.x)) + bb.x;
                float y = fmaxf(fmaxf(mx[mt][nt][2 * h + 1], v2.y), fmaxf(v5.y, v6.y)) + bb.y;
                *(float2*)(out + (size_t)b * Nn * OUTd + off) = make_float2(x, y);
            }
        }
    }
}

// ---------------------------------------------------------------------------
extern "C" void kernel_launch(void* const* d_in, const int* in_sizes, int n_in,
                              void* d_out, int out_size) {
    const float* X    = (const float*)d_in[0];
    const float* A1   = (const float*)d_in[1];
    const float* A2   = (const float*)d_in[2];
    const float* W    = (const float*)d_in[3];
    const float* We   = (const float*)d_in[4];
    const float* bias = (const float*)d_in[5];
    float* out = (float*)d_out;

    const int smem = SMEM_FLOATS * sizeof(float);
    cudaFuncSetAttribute(hw_mma,  cudaFuncAttributeMaxDynamicSharedMemorySize, smem);
    cudaFuncSetAttribute(agg_mma, cudaFuncAttributeMaxDynamicSharedMemorySize, smem);

    c_kernel<<<Rr, OUTd>>>(W, We);

    dim3 gHW(14, 64);          // 1792/128 col tiles, 8192/128 row tiles
    hw_mma<<<gHW, 256, smem>>>(X, W);

    dim3 gAgg(2, 8, Bx);       // 256/128 o-tiles, 1024/128 n-tiles, 8 batches
    agg_mma<<<gAgg, 256, smem>>>(A1, A2, bias, out);
}

// round 4
// speedup vs baseline: 4.1556x; 1.6244x over previous
#include <cuda_runtime.h>
#include <cstdint>
#include <cfloat>

#define Bx 8
#define Nn 1024
#define Fdim 256
#define OUTd 256
#define RELd 16
#define Rr 7

#define KC 32
#define SA_STR 36     // sA[n][k]  (row-major A), pad 4 (144B rows, 16B aligned)
#define ST_STR 136    // sAT[k][n] / sB[k][o], pad 8 (544B rows, 16B aligned)

#define ABUF 4608
#define BBUF 4352
#define SMEM_FLOATS (2 * ABUF + 2 * BBUF)   // 17920 floats = 71680 B

#define PSTR (Bx * Nn * OUTd)               // 2,097,152

// H[r][b][n][o] (tf32-rounded at store), P[p][b][n][o] partials
__device__ float g_H[Rr * Bx * Nn * OUTd];  // 56 MB
__device__ float g_P[4 * PSTR];             // 32 MB

__device__ __forceinline__ float to_tf32(float x) {
    float y; asm("cvt.rna.tf32.f32 %0, %1;" : "=f"(y) : "f"(x)); return y;
}
__device__ __forceinline__ float4 round4(float4 v) {
    v.x = to_tf32(v.x); v.y = to_tf32(v.y); v.z = to_tf32(v.z); v.w = to_tf32(v.w);
    return v;
}
__device__ __forceinline__ void mma8(float* c, const uint32_t* a, uint32_t b0, uint32_t b1) {
    asm volatile(
        "mma.sync.aligned.m16n8k8.row.col.f32.tf32.tf32.f32 "
        "{%0,%1,%2,%3}, {%4,%5,%6,%7}, {%8,%9}, {%0,%1,%2,%3};"
        : "+f"(c[0]), "+f"(c[1]), "+f"(c[2]), "+f"(c[3])
        : "r"(a[0]), "r"(a[1]), "r"(a[2]), "r"(a[3]), "r"(b0), "r"(b1));
}
__device__ __forceinline__ uint32_t fbits(const float* p) { return *(const uint32_t*)p; }
__device__ __forceinline__ uint32_t smem_u32(const void* p) {
    uint32_t a;
    asm("{ .reg .u64 t; cvta.to.shared.u64 t, %1; cvt.u32.u64 %0, t; }" : "=r"(a) : "l"(p));
    return a;
}
#define CPA16(dst, src) \
    asm volatile("cp.async.cg.shared.global [%0], [%1], 16;" :: "r"(dst), "l"(src))
#define CPA_COMMIT() asm volatile("cp.async.commit_group;" ::: "memory")
#define CPA_WAIT1()  asm volatile("cp.async.wait_group 1;" ::: "memory")
#define CPA_WAIT0()  asm volatile("cp.async.wait_group 0;" ::: "memory")

// ---------------------------------------------------------------------------
// HW GEMM: g_H[r][b][n][o] = tf32( X[b,n,:]@W[r][:F] + c[r] ).  Tile 128x128.
__global__ __launch_bounds__(256) void hw_mma(const float* __restrict__ X,
                                              const float* __restrict__ W,
                                              const float* __restrict__ We) {
    extern __shared__ float sm[];
    __shared__ float sCv[128];
    float* sA[2] = { sm, sm + ABUF };
    float* sB[2] = { sm + 2 * ABUF, sm + 2 * ABUF + BBUF };

    const int tid = threadIdx.x, lane = tid & 31, wid = tid >> 5;
    const int warp_m = (wid & 3) * 32, warp_n = (wid >> 2) * 64;
    const int grp = lane >> 2, tg = lane & 3;

    const int col0 = blockIdx.x * 128;
    const int m0   = blockIdx.y * 128;
    const int r    = col0 >> 8;
    const int o0   = col0 & 255;
    const float* Wr = W + (size_t)r * (Fdim + RELd) * OUTd;

    // inline edge-constant: c[r][o] = sum_d We[r,d] * W[r, F+d, o]
    if (tid < 128) {
        float s = 0.f;
#pragma unroll
        for (int d = 0; d < RELd; d++)
            s += We[r * RELd + d] * Wr[(size_t)(Fdim + d) * OUTd + o0 + tid];
        sCv[tid] = s;
    }

    float acc[2][8][4];
#pragma unroll
    for (int mt = 0; mt < 2; mt++)
#pragma unroll
        for (int nt = 0; nt < 8; nt++)
#pragma unroll
            for (int j = 0; j < 4; j++) acc[mt][nt][j] = 0.f;

#pragma unroll
    for (int i = 0; i < 4; i++) {
        int f = tid + i * 256, m = f >> 3, k4 = (f & 7) << 2;
        float4 v = round4(*(const float4*)(X + (size_t)(m0 + m) * Fdim + k4));
        *(float4*)(sA[0] + m * SA_STR + k4) = v;
        int kb = f >> 5, ob4 = (f & 31) << 2;
        float4 w = round4(*(const float4*)(Wr + (size_t)kb * OUTd + o0 + ob4));
        *(float4*)(sB[0] + kb * ST_STR + ob4) = w;
    }
    __syncthreads();

    const int NC = Fdim / KC;  // 8
    for (int c = 0; c < NC; c++) {
        const int buf = c & 1;
        float4 ra[4], rb[4];
        const bool pre = (c + 1 < NC);
        if (pre) {
            const int k0 = (c + 1) * KC;
#pragma unroll
            for (int i = 0; i < 4; i++) {
                int f = tid + i * 256, m = f >> 3, k4 = (f & 7) << 2;
                ra[i] = *(const float4*)(X + (size_t)(m0 + m) * Fdim + k0 + k4);
                int kb = f >> 5, ob4 = (f & 31) << 2;
                rb[i] = *(const float4*)(Wr + (size_t)(k0 + kb) * OUTd + o0 + ob4);
            }
        }
        const float* cA = sA[buf];
        const float* cB = sB[buf];
#pragma unroll
        for (int ks = 0; ks < 4; ks++) {
            const int k = ks * 8;
            uint32_t afr[2][4];
#pragma unroll
            for (int mt = 0; mt < 2; mt++) {
                int rr = warp_m + mt * 16 + grp, cc = k + tg;
                afr[mt][0] = fbits(cA + rr * SA_STR + cc);
                afr[mt][1] = fbits(cA + (rr + 8) * SA_STR + cc);
                afr[mt][2] = fbits(cA + rr * SA_STR + cc + 4);
                afr[mt][3] = fbits(cA + (rr + 8) * SA_STR + cc + 4);
            }
#pragma unroll
            for (int nt = 0; nt < 8; nt++) {
                int o = warp_n + nt * 8 + grp;
                uint32_t b0 = fbits(cB + (k + tg) * ST_STR + o);
                uint32_t b1 = fbits(cB + (k + tg + 4) * ST_STR + o);
                mma8(acc[0][nt], afr[0], b0, b1);
                mma8(acc[1][nt], afr[1], b0, b1);
            }
        }
        if (pre) {
            float* nA = sA[buf ^ 1];
            float* nB = sB[buf ^ 1];
#pragma unroll
            for (int i = 0; i < 4; i++) {
                int f = tid + i * 256, m = f >> 3, k4 = (f & 7) << 2;
                *(float4*)(nA + m * SA_STR + k4) = round4(ra[i]);
                int kb = f >> 5, ob4 = (f & 31) << 2;
                *(float4*)(nB + kb * ST_STR + ob4) = round4(rb[i]);
            }
            __syncthreads();
        }
    }

    // epilogue: += c[r], round to tf32, store g_H
#pragma unroll
    for (int mt = 0; mt < 2; mt++) {
#pragma unroll
        for (int nt = 0; nt < 8; nt++) {
            const int ol = warp_n + nt * 8 + 2 * tg;
            const float2 cv = *(const float2*)(sCv + ol);
            const int o = o0 + ol;
            int mg = m0 + warp_m + mt * 16 + grp;
            int b = mg >> 10, n = mg & 1023;
            float* dst = g_H + (((size_t)(r * Bx + b) * Nn + n) * OUTd) + o;
            *(float2*)dst = make_float2(to_tf32(acc[mt][nt][0] + cv.x),
                                        to_tf32(acc[mt][nt][1] + cv.y));
            mg += 8; b = mg >> 10; n = mg & 1023;
            dst = g_H + (((size_t)(r * Bx + b) * Nn + n) * OUTd) + o;
            *(float2*)dst = make_float2(to_tf32(acc[mt][nt][2] + cv.x),
                                        to_tf32(acc[mt][nt][3] + cv.y));
        }
    }
}

// ---------------------------------------------------------------------------
// One relation pass: P[p][b] = A(_or_At) @ H[hwr].  cp.async double-buffered.
template <bool TR>
__device__ __forceinline__ void agg_load(uint32_t sa, uint32_t sb,
                                         const float* Ab, const float* Hb,
                                         int n0, int o0, int k0, int tid) {
#pragma unroll
    for (int i = 0; i < 4; i++) {
        int f = tid + i * 256;
        if (!TR) {
            int m = f >> 3, k4 = (f & 7) << 2;
            CPA16(sa + (m * SA_STR + k4) * 4, Ab + (size_t)(n0 + m) * Nn + k0 + k4);
        } else {
            int kk = f >> 5, n4 = (f & 31) << 2;
            CPA16(sa + (kk * ST_STR + n4) * 4, Ab + (size_t)(k0 + kk) * Nn + n0 + n4);
        }
        int kb = f >> 5, ob4 = (f & 31) << 2;
        CPA16(sb + (kb * ST_STR + ob4) * 4, Hb + (size_t)(k0 + kb) * OUTd + o0 + ob4);
    }
}

template <bool TR>
__device__ __forceinline__ void agg_body(const float* Ab, const float* Hb,
                                         float* Pout, int n0, int o0) {
    extern __shared__ float sm[];
    float* sA[2] = { sm, sm + ABUF };
    float* sB[2] = { sm + 2 * ABUF, sm + 2 * ABUF + BBUF };
    const uint32_t saU[2] = { smem_u32(sA[0]), smem_u32(sA[1]) };
    const uint32_t sbU[2] = { smem_u32(sB[0]), smem_u32(sB[1]) };

    const int tid = threadIdx.x, lane = tid & 31, wid = tid >> 5;
    const int warp_m = (wid & 3) * 32, warp_n = (wid >> 2) * 64;
    const int grp = lane >> 2, tg = lane & 3;

    float acc[2][8][4];
#pragma unroll
    for (int mt = 0; mt < 2; mt++)
#pragma unroll
        for (int nt = 0; nt < 8; nt++)
#pragma unroll
            for (int j = 0; j < 4; j++) acc[mt][nt][j] = 0.f;

    const int NC = Nn / KC;  // 32
    agg_load<TR>(saU[0], sbU[0], Ab, Hb, n0, o0, 0, tid);
    CPA_COMMIT();
    agg_load<TR>(saU[1], sbU[1], Ab, Hb, n0, o0, KC, tid);
    CPA_COMMIT();

    for (int c = 0; c < NC; c++) {
        const int buf = c & 1;
        if (c + 1 < NC) CPA_WAIT1(); else CPA_WAIT0();
        __syncthreads();

        const float* cA = sA[buf];
        const float* cB = sB[buf];
#pragma unroll
        for (int ks = 0; ks < 4; ks++) {
            const int k = ks * 8;
            uint32_t afr[2][4];
#pragma unroll
            for (int mt = 0; mt < 2; mt++) {
                int rr = warp_m + mt * 16 + grp, cc = k + tg;
                if (!TR) {
                    afr[mt][0] = fbits(cA + rr * SA_STR + cc);
                    afr[mt][1] = fbits(cA + (rr + 8) * SA_STR + cc);
                    afr[mt][2] = fbits(cA + rr * SA_STR + cc + 4);
                    afr[mt][3] = fbits(cA + (rr + 8) * SA_STR + cc + 4);
                } else {
                    afr[mt][0] = fbits(cA + cc * ST_STR + rr);
                    afr[mt][1] = fbits(cA + cc * ST_STR + rr + 8);
                    afr[mt][2] = fbits(cA + (cc + 4) * ST_STR + rr);
                    afr[mt][3] = fbits(cA + (cc + 4) * ST_STR + rr + 8);
                }
            }
#pragma unroll
            for (int nt = 0; nt < 8; nt++) {
                int o = warp_n + nt * 8 + grp;
                uint32_t b0 = fbits(cB + (k + tg) * ST_STR + o);
                uint32_t b1 = fbits(cB + (k + tg + 4) * ST_STR + o);
                mma8(acc[0][nt], afr[0], b0, b1);
                mma8(acc[1][nt], afr[1], b0, b1);
            }
        }
        if (c + 2 < NC) {
            __syncthreads();                 // all warps done with buf before overwrite
            agg_load<TR>(saU[buf], sbU[buf], Ab, Hb, n0, o0, (c + 2) * KC, tid);
            CPA_COMMIT();
        }
    }

    // store partials
#pragma unroll
    for (int mt = 0; mt < 2; mt++) {
#pragma unroll
        for (int nt = 0; nt < 8; nt++) {
            const int o = o0 + warp_n + nt * 8 + 2 * tg;
#pragma unroll
            for (int h = 0; h < 2; h++) {
                const int n = n0 + warp_m + mt * 16 + grp + h * 8;
                *(float2*)(Pout + (size_t)n * OUTd + o) =
                    make_float2(acc[mt][nt][2 * h], acc[mt][nt][2 * h + 1]);
            }
        }
    }
}

__global__ __launch_bounds__(256, 2) void agg_pass(const float* __restrict__ A1,
                                                   const float* __restrict__ A2) {
    const int o0 = blockIdx.x * 128;
    const int n0 = blockIdx.y * 128;
    const int z  = blockIdx.z;
    const int b  = z & 7;
    const int p  = z >> 3;                   // 0: A1@H0, 1: A2@H1, 2: A1t@H3, 3: A2t@H4
    const int q  = p & 1;
    const float* Ab = (q == 0 ? A1 : A2) + (size_t)b * Nn * Nn;
    const int hwr = (p >> 1) * 3 + q;        // 0,1,3,4
    const float* Hb = g_H + ((size_t)(hwr * Bx + b) * Nn) * OUTd;
    float* Pout = g_P + (size_t)p * PSTR + ((size_t)b * Nn) * OUTd;

    if (p < 2) agg_body<false>(Ab, Hb, Pout, n0, o0);
    else       agg_body<true >(Ab, Hb, Pout, n0, o0);
}

// ---------------------------------------------------------------------------
// out = max(P0..P3, H2, H5, H6) + bias
__global__ __launch_bounds__(256) void fold_kernel(const float* __restrict__ bias,
                                                   float* __restrict__ out) {
    const int idx = (blockIdx.x * 256 + threadIdx.x) * 4;    // over 8*1024*256
    float4 v = *(const float4*)(g_P + idx);
    float4 t;
#pragma unroll
    for (int p = 1; p < 4; p++) {
        t = *(const float4*)(g_P + (size_t)p * PSTR + idx);
        v.x = fmaxf(v.x, t.x); v.y = fmaxf(v.y, t.y);
        v.z = fmaxf(v.z, t.z); v.w = fmaxf(v.w, t.w);
    }
#pragma unroll
    for (int rr = 0; rr < 3; rr++) {
        const int r = (rr == 0) ? 2 : (rr == 1) ? 5 : 6;
        t = *(const float4*)(g_H + (size_t)r * PSTR + idx);
        v.x = fmaxf(v.x, t.x); v.y = fmaxf(v.y, t.y);
        v.z = fmaxf(v.z, t.z); v.w = fmaxf(v.w, t.w);
    }
    const int bi = idx & (Nn * OUTd - 1);
    t = *(const float4*)(bias + bi);
    v.x += t.x; v.y += t.y; v.z += t.z; v.w += t.w;
    *(float4*)(out + idx) = v;
}

// ---------------------------------------------------------------------------
extern "C" void kernel_launch(void* const* d_in, const int* in_sizes, int n_in,
                              void* d_out, int out_size) {
    const float* X    = (const float*)d_in[0];
    const float* A1   = (const float*)d_in[1];
    const float* A2   = (const float*)d_in[2];
    const float* W    = (const float*)d_in[3];
    const float* We   = (const float*)d_in[4];
    const float* bias = (const float*)d_in[5];
    float* out = (float*)d_out;

    const int smem = SMEM_FLOATS * sizeof(float);
    cudaFuncSetAttribute(hw_mma,   cudaFuncAttributeMaxDynamicSharedMemorySize, smem);
    cudaFuncSetAttribute(agg_pass, cudaFuncAttributeMaxDynamicSharedMemorySize, smem);

    dim3 gHW(14, 64);
    hw_mma<<<gHW, 256, smem>>>(X, W, We);

    dim3 gAgg(2, 8, 32);       // o-tiles, n-tiles, (p<<3)|b
    agg_pass<<<gAgg, 256, smem>>>(A1, A2);

    fold_kernel<<<(Bx * Nn * OUTd) / 1024, 256>>>(bias, out);
}